// round 1
// baseline (speedup 1.0000x reference)
#include <cuda_runtime.h>
#include <cstdint>

// ---------------- problem constants ----------------
constexpr int NODES  = 100000;
constexpr int EDGES  = 500000;
constexpr int ETYPES = 3;
constexpr int FEAT   = 256;   // F == H*D
constexpr int HEADS  = 4;
constexpr int CLASSES = 349;
constexpr float NEG_SLOPE = 0.2f;

// ---------------- device scratch (allocation-free) ----------------
__device__ float    g_h[(size_t)NODES * FEAT];      // hidden state between layers
__device__ float    g_feat[(size_t)NODES * FEAT];   // per-etype transformed features
__device__ float    g_agg[(size_t)NODES * FEAT];    // summed aggregation across etypes
__device__ float    g_el[NODES * HEADS];
__device__ float    g_er[NODES * HEADS];
__device__ unsigned g_m[NODES * HEADS];             // encoded-float max
__device__ float    g_denom[NODES * HEADS];
__device__ float    g_att[(size_t)EDGES * HEADS];   // logits -> exp values

// monotone float <-> uint encoding for atomicMax on floats (incl. negatives)
__device__ __forceinline__ unsigned fenc(float f) {
    unsigned u = __float_as_uint(f);
    return (u & 0x80000000u) ? ~u : (u | 0x80000000u);
}
__device__ __forceinline__ float fdec(unsigned u) {
    return __uint_as_float((u & 0x80000000u) ? (u ^ 0x80000000u) : ~u);
}
// fenc(-inf) == 0x007fffff
#define ENC_NEG_INF 0x007fffffu

// vector float4 reduction to global (sm_90+)
__device__ __forceinline__ void red4(float* p, float a, float b, float c, float d) {
    asm volatile("red.global.add.v4.f32 [%0], {%1,%2,%3,%4};"
                 :: "l"(p), "f"(a), "f"(b), "f"(c), "f"(d) : "memory");
}

// ---------------- GEMM: C[M,Ncols] = A[M,256] @ B[256,Ncols] (+bias) ----------------
// BM=128, BN=64, BK=16, 256 threads, 8x4 per thread
__global__ void __launch_bounds__(256) gemm_k256(
    const float* __restrict__ A, const float* __restrict__ B,
    float* __restrict__ C, const float* __restrict__ bias,
    int M, int Ncols)
{
    __shared__ float As[16][128];
    __shared__ float Bs[16][64];
    const int K = 256;
    int tid = threadIdx.x;
    int tx = tid & 15;   // col group
    int ty = tid >> 4;   // row group
    long bm = (long)blockIdx.x * 128;
    int bn  = blockIdx.y * 64;

    float acc[8][4];
#pragma unroll
    for (int i = 0; i < 8; i++)
#pragma unroll
        for (int j = 0; j < 4; j++) acc[i][j] = 0.f;

    int a_r0 = tid >> 2;        // 0..63
    int a_c  = (tid & 3) * 4;   // 0,4,8,12
    int b_r  = tid >> 4;        // 0..15
    int b_c  = (tid & 15) * 4;  // 0..60
    bool bvec = ((Ncols & 3) == 0);

    for (int k0 = 0; k0 < K; k0 += 16) {
        // load A tile (128 x 16), two float4 per thread
#pragma unroll
        for (int q = 0; q < 2; q++) {
            int r = a_r0 + q * 64;
            float4 av = make_float4(0.f, 0.f, 0.f, 0.f);
            if (bm + r < M)
                av = *reinterpret_cast<const float4*>(A + (bm + r) * K + k0 + a_c);
            As[a_c + 0][r] = av.x;
            As[a_c + 1][r] = av.y;
            As[a_c + 2][r] = av.z;
            As[a_c + 3][r] = av.w;
        }
        // load B tile (16 x 64)
        {
            int col = bn + b_c;
            const float* brow = B + (long)(k0 + b_r) * Ncols;
            if (bvec && (col + 3) < Ncols) {
                float4 bv = *reinterpret_cast<const float4*>(brow + col);
                Bs[b_r][b_c + 0] = bv.x;
                Bs[b_r][b_c + 1] = bv.y;
                Bs[b_r][b_c + 2] = bv.z;
                Bs[b_r][b_c + 3] = bv.w;
            } else {
#pragma unroll
                for (int j = 0; j < 4; j++)
                    Bs[b_r][b_c + j] = ((col + j) < Ncols) ? brow[col + j] : 0.f;
            }
        }
        __syncthreads();
#pragma unroll
        for (int k = 0; k < 16; k++) {
            float4 a0 = *reinterpret_cast<const float4*>(&As[k][ty * 8]);
            float4 a1 = *reinterpret_cast<const float4*>(&As[k][ty * 8 + 4]);
            float4 bv = *reinterpret_cast<const float4*>(&Bs[k][tx * 4]);
            float a[8] = {a0.x, a0.y, a0.z, a0.w, a1.x, a1.y, a1.z, a1.w};
            float b[4] = {bv.x, bv.y, bv.z, bv.w};
#pragma unroll
            for (int i = 0; i < 8; i++)
#pragma unroll
                for (int j = 0; j < 4; j++)
                    acc[i][j] += a[i] * b[j];
        }
        __syncthreads();
    }
#pragma unroll
    for (int i = 0; i < 8; i++) {
        long row = bm + ty * 8 + i;
        if (row >= M) continue;
#pragma unroll
        for (int j = 0; j < 4; j++) {
            int col = bn + tx * 4 + j;
            if (col < Ncols) {
                float v = acc[i][j];
                if (bias) v += bias[col];
                C[row * Ncols + col] = v;
            }
        }
    }
}

// ---------------- per-node attention dots + reset m/denom ----------------
// one warp per node; lane l covers dims [8l, 8l+8) -> head = l>>3
__global__ void __launch_bounds__(256) node_att(
    const float* __restrict__ feat,
    const float* __restrict__ al, const float* __restrict__ ar,
    float* __restrict__ el, float* __restrict__ er,
    unsigned* __restrict__ m, float* __restrict__ denom)
{
    int warp = (blockIdx.x * blockDim.x + threadIdx.x) >> 5;
    int lane = threadIdx.x & 31;
    if (warp >= NODES) return;
    const float4* frow = reinterpret_cast<const float4*>(feat + (long)warp * FEAT);
    const float4* alv  = reinterpret_cast<const float4*>(al);
    const float4* arv  = reinterpret_cast<const float4*>(ar);
    float sl = 0.f, sr = 0.f;
#pragma unroll
    for (int q = 0; q < 2; q++) {
        int idx = lane * 2 + q;
        float4 f = frow[idx], a = alv[idx], b = arv[idx];
        sl += f.x * a.x + f.y * a.y + f.z * a.z + f.w * a.w;
        sr += f.x * b.x + f.y * b.y + f.z * b.z + f.w * b.w;
    }
    // reduce within 8-lane groups (one head per group)
#pragma unroll
    for (int off = 4; off >= 1; off >>= 1) {
        sl += __shfl_xor_sync(0xffffffffu, sl, off);
        sr += __shfl_xor_sync(0xffffffffu, sr, off);
    }
    if ((lane & 7) == 0) {
        int h = lane >> 3;
        el[warp * HEADS + h] = sl;
        er[warp * HEADS + h] = sr;
    }
    if (lane < HEADS) {
        m[warp * HEADS + lane] = ENC_NEG_INF;
        denom[warp * HEADS + lane] = 0.f;
    }
}

// ---------------- edge pass 1: logits + segment max ----------------
__global__ void __launch_bounds__(256) edge_max(
    const int* __restrict__ src, const int* __restrict__ dst,
    const float* __restrict__ el, const float* __restrict__ er,
    float* __restrict__ att, unsigned* __restrict__ m)
{
    int e = blockIdx.x * blockDim.x + threadIdx.x;
    if (e >= EDGES) return;
    int s = src[e], d = dst[e];
    float4 a = *reinterpret_cast<const float4*>(el + (long)s * 4);
    float4 b = *reinterpret_cast<const float4*>(er + (long)d * 4);
    float lg[4] = {a.x + b.x, a.y + b.y, a.z + b.z, a.w + b.w};
#pragma unroll
    for (int h = 0; h < 4; h++) {
        float v = lg[h] > 0.f ? lg[h] : NEG_SLOPE * lg[h];
        lg[h] = v;
        atomicMax(m + (long)d * 4 + h, fenc(v));
    }
    *reinterpret_cast<float4*>(att + (long)e * 4) = make_float4(lg[0], lg[1], lg[2], lg[3]);
}

// ---------------- edge pass 2: exp + segment sum (denom) ----------------
__global__ void __launch_bounds__(256) edge_exp(
    const int* __restrict__ dst, float* __restrict__ att,
    const unsigned* __restrict__ m, float* __restrict__ denom)
{
    int e = blockIdx.x * blockDim.x + threadIdx.x;
    if (e >= EDGES) return;
    int d = dst[e];
    float4 lg = *reinterpret_cast<const float4*>(att + (long)e * 4);
    uint4 mu = *reinterpret_cast<const uint4*>(m + (long)d * 4);
    float a0 = __expf(lg.x - fdec(mu.x));
    float a1 = __expf(lg.y - fdec(mu.y));
    float a2 = __expf(lg.z - fdec(mu.z));
    float a3 = __expf(lg.w - fdec(mu.w));
    atomicAdd(denom + (long)d * 4 + 0, a0);
    atomicAdd(denom + (long)d * 4 + 1, a1);
    atomicAdd(denom + (long)d * 4 + 2, a2);
    atomicAdd(denom + (long)d * 4 + 3, a3);
    *reinterpret_cast<float4*>(att + (long)e * 4) = make_float4(a0, a1, a2, a3);
}

// ---------------- edge pass 3: alpha * feat[src] scattered to agg[dst] ----------------
// one warp per edge; lane l covers dims [4l,4l+4) and [128+4l,128+4l+4)
__global__ void __launch_bounds__(256) edge_agg(
    const int* __restrict__ src, const int* __restrict__ dst,
    const float* __restrict__ att, const float* __restrict__ denom,
    const float* __restrict__ feat, float* __restrict__ agg)
{
    int warp = (blockIdx.x * blockDim.x + threadIdx.x) >> 5;
    int lane = threadIdx.x & 31;
    if (warp >= EDGES) return;
    int s = src[warp], d = dst[warp];
    float alpha = 0.f;
    if (lane < 4)
        alpha = att[(long)warp * 4 + lane] / denom[(long)d * 4 + lane];
    int h0 = lane >> 4;  // head of first chunk (0 or 1)
    float al0 = __shfl_sync(0xffffffffu, alpha, h0);
    float al1 = __shfl_sync(0xffffffffu, alpha, h0 + 2);
    const float4* fs = reinterpret_cast<const float4*>(feat + (long)s * FEAT);
    float4 f0 = fs[lane];
    float4 f1 = fs[lane + 32];
    float* base = agg + (long)d * FEAT;
    red4(base + lane * 4,       al0 * f0.x, al0 * f0.y, al0 * f0.z, al0 * f0.w);
    red4(base + 128 + lane * 4, al1 * f1.x, al1 * f1.y, al1 * f1.z, al1 * f1.w);
}

// ---------------- zero fill ----------------
__global__ void __launch_bounds__(256) zero_f4(float* __restrict__ p, int n4) {
    int i = blockIdx.x * blockDim.x + threadIdx.x;
    if (i < n4) reinterpret_cast<float4*>(p)[i] = make_float4(0.f, 0.f, 0.f, 0.f);
}

// ---------------- finalize: h_out = act(agg + sum_e bias[l,e]) ----------------
__global__ void __launch_bounds__(256) finalize(
    const float* __restrict__ agg, const float* __restrict__ bias_l,
    float* __restrict__ hout, int do_relu)
{
    long i = (long)blockIdx.x * blockDim.x + threadIdx.x;
    if (i >= (long)NODES * FEAT) return;
    int col = (int)(i & 255);
    float b = bias_l[col] + bias_l[256 + col] + bias_l[512 + col];
    float v = agg[i] + b;
    if (do_relu) v = fmaxf(v, 0.f);
    hout[i] = v;
}

// ---------------- launch ----------------
extern "C" void kernel_launch(void* const* d_in, const int* in_sizes, int n_in,
                              void* d_out, int out_size)
{
    const float* x      = (const float*)d_in[0];
    const float* W      = (const float*)d_in[1];
    const float* attn_l = (const float*)d_in[2];
    const float* attn_r = (const float*)d_in[3];
    const float* bias   = (const float*)d_in[4];
    const float* W_out  = (const float*)d_in[5];
    const float* b_out  = (const float*)d_in[6];
    const int*   src    = (const int*)d_in[7];
    const int*   dst    = (const int*)d_in[8];

    float *hbuf, *feat, *agg, *el, *er, *denom, *att;
    unsigned* m;
    cudaGetSymbolAddress((void**)&hbuf,  g_h);
    cudaGetSymbolAddress((void**)&feat,  g_feat);
    cudaGetSymbolAddress((void**)&agg,   g_agg);
    cudaGetSymbolAddress((void**)&el,    g_el);
    cudaGetSymbolAddress((void**)&er,    g_er);
    cudaGetSymbolAddress((void**)&m,     g_m);
    cudaGetSymbolAddress((void**)&denom, g_denom);
    cudaGetSymbolAddress((void**)&att,   g_att);

    const int GEMM_GRID_M = (NODES + 127) / 128;  // 782
    dim3 gemm_feat_grid(GEMM_GRID_M, FEAT / 64);            // x64 -> 4
    dim3 gemm_out_grid(GEMM_GRID_M, (CLASSES + 63) / 64);   // -> 6

    const float* hin = x;
    for (int l = 0; l < 2; l++) {
        zero_f4<<<(NODES * FEAT / 4 + 255) / 256, 256>>>(agg, NODES * FEAT / 4);
        for (int e = 0; e < ETYPES; e++) {
            int le = l * ETYPES + e;
            const float* Wle = W + (long)le * FEAT * FEAT;
            gemm_k256<<<gemm_feat_grid, 256>>>(hin, Wle, feat, nullptr, NODES, FEAT);
            node_att<<<(NODES * 32 + 255) / 256, 256>>>(
                feat, attn_l + le * FEAT, attn_r + le * FEAT, el, er, m, denom);
            const int* se = src + (long)e * EDGES;
            const int* de = dst + (long)e * EDGES;
            edge_max<<<(EDGES + 255) / 256, 256>>>(se, de, el, er, att, m);
            edge_exp<<<(EDGES + 255) / 256, 256>>>(de, att, m, denom);
            edge_agg<<<(EDGES * 32 + 255) / 256, 256>>>(se, de, att, denom, feat, agg);
        }
        finalize<<<((long)NODES * FEAT + 255) / 256, 256>>>(
            agg, bias + l * ETYPES * FEAT, hbuf, (l == 0) ? 1 : 0);
        hin = hbuf;
    }
    gemm_k256<<<gemm_out_grid, 256>>>(hin, W_out, (float*)d_out, b_out, NODES, CLASSES);
}